// round 9
// baseline (speedup 1.0000x reference)
#include <cuda_runtime.h>
#include <cstdint>

constexpr int B = 8192;    // batch
constexpr int D = 4096;    // features
constexpr int H = 2048;    // hidden
constexpr int HW = H / 32; // 64 packed words

// Device-global scratch (no runtime allocation allowed)
__device__ uint32_t g_Wcols[D * HW];     // Wb column d packed along h (1 MB)
__device__ float    g_template[D];       // layer-2 output row for all-ones h
__device__ uint32_t g_m1[HW], g_m2[HW], g_m3[HW], g_m4[HW], g_mall[HW];
__device__ int      g_t2[D];
__device__ int      g_t1u;               // uniform layer-1 threshold in {1,2}, else -1

// ---------------------------------------------------------------------------
// Kernel 1: pack W (blocks 0..2047, round-6 measured-fastest pattern:
// scalar column reads, one 16-bit halfword per thread) + thresholds/masks
// (block 2048).
// ---------------------------------------------------------------------------
__global__ void __launch_bounds__(256) pack_kernel(const float* __restrict__ W,
                                                   const float* __restrict__ be,
                                                   const float* __restrict__ b0,
                                                   const float* __restrict__ b3) {
    if (blockIdx.x < 2048) {
        int g = blockIdx.x * 256 + threadIdx.x;  // 524288 threads
        int part = g >> 12;          // 0..127 : w*2 + half
        int d    = g & (D - 1);      // column, consecutive within warp (coalesced)
        int w    = part >> 1;
        int half = part & 1;
        int h0   = w * 32 + half * 16;

        uint32_t u = 0;
#pragma unroll
        for (int r = 0; r < 16; r++) {
            float f = __ldcs(&W[(size_t)(h0 + r) * D + d]);
            if (f >= 0.5f) u |= (1u << r);
        }
        reinterpret_cast<uint16_t*>(g_Wcols)[(d * HW + w) * 2 + half] = (uint16_t)u;
    } else {
        __shared__ int s_ok;
        int t = threadIdx.x;
        if (t == 0) s_ok = 1;
        __syncthreads();

        int t0 = (int)ceilf(1.0f - be[0] - b0[0]);

        if (t < HW) {
            uint32_t m1 = 0, m2 = 0, m3 = 0, m4 = 0, mall = 0;
#pragma unroll
            for (int bit = 0; bit < 32; bit++) {
                int h = t * 32 + bit;
                int ti = (int)ceilf(1.0f - be[h] - b0[h]);
                uint32_t m = 1u << bit;
                if (ti <= 0)      mall |= m;
                else if (ti == 1) m1 |= m;
                else if (ti == 2) m2 |= m;
                else if (ti == 3) m3 |= m;
                else if (ti == 4) m4 |= m;
            }
            g_m1[t] = m1; g_m2[t] = m2; g_m3[t] = m3; g_m4[t] = m4; g_mall[t] = mall;
        }

        int ok = 1;
        for (int h = t; h < H; h += 256) {
            int ti = (int)ceilf(1.0f - be[h] - b0[h]);
            if (ti != t0) ok = 0;
        }
        if (!ok) s_ok = 0;   // benign race, all writers store 0

        for (int d = t; d < D; d += 256)
            g_t2[d] = (int)ceilf(1.0f - b3[d]);

        __syncthreads();
        if (t == 0) g_t1u = (s_ok && t0 >= 1 && t0 <= 2) ? t0 : -1;
    }
}

// ---------------------------------------------------------------------------
// Kernel 2: template output row for all-ones h: (popc(Wcol[d]) >= t2[d]).
// ---------------------------------------------------------------------------
__global__ void template_kernel() {
    int d = blockIdx.x * blockDim.x + threadIdx.x;
    const uint4* col = reinterpret_cast<const uint4*>(g_Wcols + (size_t)d * HW);
    int c = 0;
#pragma unroll
    for (int i = 0; i < HW / 4; i++) {
        uint4 v = col[i];
        c += __popc(v.x) + __popc(v.y) + __popc(v.z) + __popc(v.w);
    }
    g_template[d] = (c >= g_t2[d]) ? 1.0f : 0.0f;
}

// ---------------------------------------------------------------------------
// Kernel 3 (fused layer1+layer2): one warp per batch row, 8 rows per block.
// Proven round-5 version (plain x loads, register template, block-cooperative
// streaming-store broadcast).
// ---------------------------------------------------------------------------
__global__ void __launch_bounds__(256) fused_kernel(const float* __restrict__ x,
                                                    float* __restrict__ out) {
    __shared__ uint32_t sh_h[8][HW];   // slow-path h bits (rarely used)
    __shared__ int sflag[8];           // per-row "broadcast template" flag
    int tid  = threadIdx.x;
    int warp = tid >> 5;
    int lane = tid & 31;
    int b = blockIdx.x * 8 + warp;

    // Preload template slice into registers (template_kernel already ran).
    const float4* tp = reinterpret_cast<const float4*>(g_template);
    float4 tpl0 = __ldg(&tp[tid]);
    float4 tpl1 = __ldg(&tp[tid + 256]);
    float4 tpl2 = __ldg(&tp[tid + 512]);
    float4 tpl3 = __ldg(&tp[tid + 768]);

    const float4* xr = reinterpret_cast<const float4*>(x + (size_t)b * D);
    const uint2*  Wc = reinterpret_cast<const uint2*>(g_Wcols);
    int uni = g_t1u;

    uint2 c1 = make_uint2(0u, 0u), c2 = make_uint2(0u, 0u);
    uint2 c3 = make_uint2(0u, 0u), c4 = make_uint2(0u, 0u);
    bool sat = false;

    float4 f = xr[lane];                       // prefetch chunk 0
    for (int i = 0; i < 32; i++) {
        float4 cur = f;
        if (i + 1 < 32) f = xr[(i + 1) * 32 + lane];   // prefetch next chunk

        uint32_t mw0 = __ballot_sync(0xffffffffu, cur.x != 0.0f);
        uint32_t mw1 = __ballot_sync(0xffffffffu, cur.y != 0.0f);
        uint32_t mw2 = __ballot_sync(0xffffffffu, cur.z != 0.0f);
        uint32_t mw3 = __ballot_sync(0xffffffffu, cur.w != 0.0f);

        if (uni >= 1) {
            // 2-plane CSA (uniform threshold 1 or 2)
#pragma unroll
            for (int j = 0; j < 4; j++) {
                uint32_t m = (j == 0) ? mw0 : (j == 1) ? mw1 : (j == 2) ? mw2 : mw3;
                while (m) {
                    int l = __ffs(m) - 1; m &= m - 1;
                    uint2 v = Wc[(i * 128 + l * 4 + j) * 32 + lane];
                    c2.x |= c1.x & v.x; c1.x |= v.x;
                    c2.y |= c1.y & v.y; c1.y |= v.y;
                }
            }
            uint32_t sw = (uni == 1) ? (c1.x & c1.y) : (c2.x & c2.y);
            if (__all_sync(0xffffffffu, sw == 0xffffffffu)) { sat = true; break; }
        } else {
            // general 4-plane saturating CSA
#pragma unroll
            for (int j = 0; j < 4; j++) {
                uint32_t m = (j == 0) ? mw0 : (j == 1) ? mw1 : (j == 2) ? mw2 : mw3;
                while (m) {
                    int l = __ffs(m) - 1; m &= m - 1;
                    uint2 v = Wc[(i * 128 + l * 4 + j) * 32 + lane];
                    c4.x |= c3.x & v.x; c3.x |= c2.x & v.x; c2.x |= c1.x & v.x; c1.x |= v.x;
                    c4.y |= c3.y & v.y; c3.y |= c2.y & v.y; c2.y |= c1.y & v.y; c1.y |= v.y;
                }
            }
            if (__all_sync(0xffffffffu, (c4.x & c4.y) == 0xffffffffu)) break;
        }
    }

    // Resolve hidden bits for this row
    uint2 hw;
    if (uni >= 1) {
        hw = sat ? make_uint2(0xffffffffu, 0xffffffffu) : ((uni == 1) ? c1 : c2);
    } else {
        int w0 = 2 * lane, w1 = 2 * lane + 1;
        hw.x = g_mall[w0] | (c1.x & g_m1[w0]) | (c2.x & g_m2[w0]) |
               (c3.x & g_m3[w0]) | (c4.x & g_m4[w0]);
        hw.y = g_mall[w1] | (c1.y & g_m1[w1]) | (c2.y & g_m2[w1]) |
               (c3.y & g_m3[w1]) | (c4.y & g_m4[w1]);
    }
    bool allones = __all_sync(0xffffffffu, (hw.x & hw.y) == 0xffffffffu);
    if (lane == 0) sflag[warp] = allones ? 1 : 0;

    if (!allones) {
        // exact path (rare): popcount h against every Wb column
        sh_h[warp][2 * lane]     = hw.x;
        sh_h[warp][2 * lane + 1] = hw.y;
        __syncwarp();
        const uint32_t* hv = sh_h[warp];
        for (int k = 0; k < D / 32; k++) {
            int d = k * 32 + lane;
            int t2 = g_t2[d];
            float val;
            if (t2 <= 0) {
                val = 1.0f;
            } else {
                const uint32_t* wv = g_Wcols + (size_t)d * HW;
                int c = 0;
                for (int w = 0; w < HW; w++) {
                    c += __popc(hv[w] & wv[w]);
                    if (c >= t2) break;
                }
                val = (c >= t2) ? 1.0f : 0.0f;
            }
            out[(size_t)b * D + d] = val;
        }
    }
    __syncthreads();

    // Block-cooperative template broadcast: pure streaming stores from regs.
#pragma unroll
    for (int r = 0; r < 8; r++) {
        if (sflag[r]) {
            float4* orow = reinterpret_cast<float4*>(out + (size_t)(blockIdx.x * 8 + r) * D);
            __stcs(&orow[tid],       tpl0);
            __stcs(&orow[tid + 256], tpl1);
            __stcs(&orow[tid + 512], tpl2);
            __stcs(&orow[tid + 768], tpl3);
        }
    }
}

// ---------------------------------------------------------------------------
extern "C" void kernel_launch(void* const* d_in, const int* in_sizes, int n_in,
                              void* d_out, int out_size) {
    const float* x     = (const float*)d_in[0];  // [B, D]
    const float* W     = (const float*)d_in[1];  // [H, D]
    const float* b_enc = (const float*)d_in[2];  // [H]
    const float* b0    = (const float*)d_in[3];  // [H]
    const float* b3    = (const float*)d_in[4];  // [D]
    float* out = (float*)d_out;                  // [B, D]

    pack_kernel<<<2049, 256>>>(W, b_enc, b0, b3);
    template_kernel<<<D / 256, 256>>>();
    fused_kernel<<<B / 8, 256>>>(x, out);
}

// round 10
// speedup vs baseline: 1.0809x; 1.0809x over previous
#include <cuda_runtime.h>
#include <cstdint>

constexpr int B = 8192;    // batch
constexpr int D = 4096;    // features
constexpr int H = 2048;    // hidden
constexpr int HW = H / 32; // 64 packed words

// Device-global scratch (no runtime allocation allowed)
__device__ uint32_t g_Wcols[D * HW];     // Wb column d packed along h (1 MB)
__device__ float    g_template[D];       // layer-2 output row for all-ones h
__device__ uint32_t g_m1[HW], g_m2[HW], g_m3[HW], g_m4[HW], g_mall[HW];
__device__ int      g_t2[D];
__device__ int      g_t1u;               // uniform layer-1 threshold in {1,2}, else -1

// ---------------------------------------------------------------------------
// Kernel 1: pack W (blocks 0..511) + thresholds/masks (block 512).
// Pack tile = 32 columns x 16 words (512 rows).  Reads: 32 consecutive d per
// warp = 128B coalesced, 64 independent loads/thread.  Words staged in padded
// smem, then written as contiguous uint4 runs -> Wcols write traffic = 1 MB
// exactly (previous rounds scattered 4B/2B stores = 16-32 MB of dirty
// sectors, which is why pack never reached DRAM rate).
// ---------------------------------------------------------------------------
__global__ void __launch_bounds__(256) pack_kernel(const float* __restrict__ W,
                                                   const float* __restrict__ be,
                                                   const float* __restrict__ b0,
                                                   const float* __restrict__ b3) {
    if (blockIdx.x < 512) {
        __shared__ uint32_t s[32][17];    // [d_local][w_local], padded
        int tile = blockIdx.x;
        int d0 = (tile >> 2) * 32;        // 128 column-groups
        int w0 = (tile & 3) * 16;         // 4 word-groups (16 words = 512 rows)
        int t  = threadIdx.x;
        int dl = t & 31;                  // lane -> column (coalesced reads)
        int wg = t >> 5;                  // warp -> 2 words (64 rows)

        const float* Wp = W + (size_t)((w0 + wg * 2) * 32) * D + d0 + dl;
#pragma unroll
        for (int k = 0; k < 2; k++) {
            uint32_t u = 0;
#pragma unroll
            for (int r = 0; r < 32; r++) {
                float f = __ldcs(Wp + (size_t)(k * 32 + r) * D);
                if (f >= 0.5f) u |= (1u << r);
            }
            s[dl][wg * 2 + k] = u;
        }
        __syncthreads();

        // Store phase: 128 threads write 128 uint4 (512 words) coalesced.
        if (t < 128) {
            int col = t >> 2;             // 0..31
            int j   = t & 3;              // 0..3 (uint4 within 16-word run)
            uint4 v = make_uint4(s[col][j * 4 + 0], s[col][j * 4 + 1],
                                 s[col][j * 4 + 2], s[col][j * 4 + 3]);
            reinterpret_cast<uint4*>(g_Wcols)[(size_t)(d0 + col) * 16 + (w0 >> 2) + j] = v;
        }
    } else {
        __shared__ int s_ok;
        int t = threadIdx.x;
        if (t == 0) s_ok = 1;
        __syncthreads();

        int t0 = (int)ceilf(1.0f - be[0] - b0[0]);

        if (t < HW) {
            uint32_t m1 = 0, m2 = 0, m3 = 0, m4 = 0, mall = 0;
#pragma unroll
            for (int bit = 0; bit < 32; bit++) {
                int h = t * 32 + bit;
                int ti = (int)ceilf(1.0f - be[h] - b0[h]);
                uint32_t m = 1u << bit;
                if (ti <= 0)      mall |= m;
                else if (ti == 1) m1 |= m;
                else if (ti == 2) m2 |= m;
                else if (ti == 3) m3 |= m;
                else if (ti == 4) m4 |= m;
            }
            g_m1[t] = m1; g_m2[t] = m2; g_m3[t] = m3; g_m4[t] = m4; g_mall[t] = mall;
        }

        int ok = 1;
        for (int h = t; h < H; h += 256) {
            int ti = (int)ceilf(1.0f - be[h] - b0[h]);
            if (ti != t0) ok = 0;
        }
        if (!ok) s_ok = 0;   // benign race, all writers store 0

        for (int d = t; d < D; d += 256)
            g_t2[d] = (int)ceilf(1.0f - b3[d]);

        __syncthreads();
        if (t == 0) g_t1u = (s_ok && t0 >= 1 && t0 <= 2) ? t0 : -1;
    }
}

// ---------------------------------------------------------------------------
// Kernel 2: template output row for all-ones h: (popc(Wcol[d]) >= t2[d]).
// ---------------------------------------------------------------------------
__global__ void template_kernel() {
    int d = blockIdx.x * blockDim.x + threadIdx.x;
    const uint4* col = reinterpret_cast<const uint4*>(g_Wcols + (size_t)d * HW);
    int c = 0;
#pragma unroll
    for (int i = 0; i < HW / 4; i++) {
        uint4 v = col[i];
        c += __popc(v.x) + __popc(v.y) + __popc(v.z) + __popc(v.w);
    }
    g_template[d] = (c >= g_t2[d]) ? 1.0f : 0.0f;
}

// ---------------------------------------------------------------------------
// Kernel 3 (fused layer1+layer2): one warp per batch row, 8 rows per block.
// Proven round-5 version (plain x loads, register template, block-cooperative
// streaming-store broadcast).
// ---------------------------------------------------------------------------
__global__ void __launch_bounds__(256) fused_kernel(const float* __restrict__ x,
                                                    float* __restrict__ out) {
    __shared__ uint32_t sh_h[8][HW];   // slow-path h bits (rarely used)
    __shared__ int sflag[8];           // per-row "broadcast template" flag
    int tid  = threadIdx.x;
    int warp = tid >> 5;
    int lane = tid & 31;
    int b = blockIdx.x * 8 + warp;

    // Preload template slice into registers (template_kernel already ran).
    const float4* tp = reinterpret_cast<const float4*>(g_template);
    float4 tpl0 = __ldg(&tp[tid]);
    float4 tpl1 = __ldg(&tp[tid + 256]);
    float4 tpl2 = __ldg(&tp[tid + 512]);
    float4 tpl3 = __ldg(&tp[tid + 768]);

    const float4* xr = reinterpret_cast<const float4*>(x + (size_t)b * D);
    const uint2*  Wc = reinterpret_cast<const uint2*>(g_Wcols);
    int uni = g_t1u;

    uint2 c1 = make_uint2(0u, 0u), c2 = make_uint2(0u, 0u);
    uint2 c3 = make_uint2(0u, 0u), c4 = make_uint2(0u, 0u);
    bool sat = false;

    float4 f = xr[lane];                       // prefetch chunk 0
    for (int i = 0; i < 32; i++) {
        float4 cur = f;
        if (i + 1 < 32) f = xr[(i + 1) * 32 + lane];   // prefetch next chunk

        uint32_t mw0 = __ballot_sync(0xffffffffu, cur.x != 0.0f);
        uint32_t mw1 = __ballot_sync(0xffffffffu, cur.y != 0.0f);
        uint32_t mw2 = __ballot_sync(0xffffffffu, cur.z != 0.0f);
        uint32_t mw3 = __ballot_sync(0xffffffffu, cur.w != 0.0f);

        if (uni >= 1) {
            // 2-plane CSA (uniform threshold 1 or 2)
#pragma unroll
            for (int j = 0; j < 4; j++) {
                uint32_t m = (j == 0) ? mw0 : (j == 1) ? mw1 : (j == 2) ? mw2 : mw3;
                while (m) {
                    int l = __ffs(m) - 1; m &= m - 1;
                    uint2 v = Wc[(i * 128 + l * 4 + j) * 32 + lane];
                    c2.x |= c1.x & v.x; c1.x |= v.x;
                    c2.y |= c1.y & v.y; c1.y |= v.y;
                }
            }
            uint32_t sw = (uni == 1) ? (c1.x & c1.y) : (c2.x & c2.y);
            if (__all_sync(0xffffffffu, sw == 0xffffffffu)) { sat = true; break; }
        } else {
            // general 4-plane saturating CSA
#pragma unroll
            for (int j = 0; j < 4; j++) {
                uint32_t m = (j == 0) ? mw0 : (j == 1) ? mw1 : (j == 2) ? mw2 : mw3;
                while (m) {
                    int l = __ffs(m) - 1; m &= m - 1;
                    uint2 v = Wc[(i * 128 + l * 4 + j) * 32 + lane];
                    c4.x |= c3.x & v.x; c3.x |= c2.x & v.x; c2.x |= c1.x & v.x; c1.x |= v.x;
                    c4.y |= c3.y & v.y; c3.y |= c2.y & v.y; c2.y |= c1.y & v.y; c1.y |= v.y;
                }
            }
            if (__all_sync(0xffffffffu, (c4.x & c4.y) == 0xffffffffu)) break;
        }
    }

    // Resolve hidden bits for this row
    uint2 hw;
    if (uni >= 1) {
        hw = sat ? make_uint2(0xffffffffu, 0xffffffffu) : ((uni == 1) ? c1 : c2);
    } else {
        int w0 = 2 * lane, w1 = 2 * lane + 1;
        hw.x = g_mall[w0] | (c1.x & g_m1[w0]) | (c2.x & g_m2[w0]) |
               (c3.x & g_m3[w0]) | (c4.x & g_m4[w0]);
        hw.y = g_mall[w1] | (c1.y & g_m1[w1]) | (c2.y & g_m2[w1]) |
               (c3.y & g_m3[w1]) | (c4.y & g_m4[w1]);
    }
    bool allones = __all_sync(0xffffffffu, (hw.x & hw.y) == 0xffffffffu);
    if (lane == 0) sflag[warp] = allones ? 1 : 0;

    if (!allones) {
        // exact path (rare): popcount h against every Wb column
        sh_h[warp][2 * lane]     = hw.x;
        sh_h[warp][2 * lane + 1] = hw.y;
        __syncwarp();
        const uint32_t* hv = sh_h[warp];
        for (int k = 0; k < D / 32; k++) {
            int d = k * 32 + lane;
            int t2 = g_t2[d];
            float val;
            if (t2 <= 0) {
                val = 1.0f;
            } else {
                const uint32_t* wv = g_Wcols + (size_t)d * HW;
                int c = 0;
                for (int w = 0; w < HW; w++) {
                    c += __popc(hv[w] & wv[w]);
                    if (c >= t2) break;
                }
                val = (c >= t2) ? 1.0f : 0.0f;
            }
            out[(size_t)b * D + d] = val;
        }
    }
    __syncthreads();

    // Block-cooperative template broadcast: pure streaming stores from regs.
#pragma unroll
    for (int r = 0; r < 8; r++) {
        if (sflag[r]) {
            float4* orow = reinterpret_cast<float4*>(out + (size_t)(blockIdx.x * 8 + r) * D);
            __stcs(&orow[tid],       tpl0);
            __stcs(&orow[tid + 256], tpl1);
            __stcs(&orow[tid + 512], tpl2);
            __stcs(&orow[tid + 768], tpl3);
        }
    }
}

// ---------------------------------------------------------------------------
extern "C" void kernel_launch(void* const* d_in, const int* in_sizes, int n_in,
                              void* d_out, int out_size) {
    const float* x     = (const float*)d_in[0];  // [B, D]
    const float* W     = (const float*)d_in[1];  // [H, D]
    const float* b_enc = (const float*)d_in[2];  // [H]
    const float* b0    = (const float*)d_in[3];  // [H]
    const float* b3    = (const float*)d_in[4];  // [D]
    float* out = (float*)d_out;                  // [B, D]

    pack_kernel<<<513, 256>>>(W, b_enc, b0, b3);
    template_kernel<<<D / 256, 256>>>();
    fused_kernel<<<B / 8, 256>>>(x, out);
}